// round 1
// baseline (speedup 1.0000x reference)
#include <cuda_runtime.h>
#include <cstdint>
#include <cstddef>

// Problem constants
#define B_  32
#define N_  3136
#define C_  384
#define H_  8
#define DH  48
#define M_  196
#define BN  100352           // B_*N_
#define SPLITS 7             // attention n-splits
#define CPS    7             // chunks (of 64) per split: 7*7*64 = 3136

// ---------------- scratch (device globals; no allocation allowed) ----------
__device__ float g_xg[(size_t)BN * C_];                         // LN+GELU output
__device__ float g_kv[(size_t)BN * 2 * C_];                     // kv projection
__device__ float g_opart[(size_t)SPLITS * B_ * H_ * M_ * DH];   // attention partial numerators
__device__ float g_den[(size_t)SPLITS * B_ * H_ * M_];          // attention partial denominators
__device__ float g_ao[(size_t)B_ * M_ * C_];                    // attention output [B,M,H,Dh]=[B*M,C]

// ---------------- helpers ---------------------------------------------------
__device__ __forceinline__ uint32_t f2tf(float f) {
    uint32_t u;
    asm("cvt.rna.tf32.f32 %0, %1;" : "=r"(u) : "f"(f));
    return u;
}

__device__ __forceinline__ void mma8(float d[4], const uint32_t a[4], const uint32_t b[2]) {
    asm("mma.sync.aligned.m16n8k8.row.col.f32.tf32.tf32.f32 "
        "{%0,%1,%2,%3},{%4,%5,%6,%7},{%8,%9},{%0,%1,%2,%3};"
        : "+f"(d[0]), "+f"(d[1]), "+f"(d[2]), "+f"(d[3])
        : "r"(a[0]), "r"(a[1]), "r"(a[2]), "r"(a[3]), "r"(b[0]), "r"(b[1]));
}

__device__ __forceinline__ float gelu_exact(float y) {
    return 0.5f * y * (1.0f + erff(y * 0.7071067811865475f));
}

// ---------------- kernel 1: LayerNorm + exact GELU ---------------------------
// one warp per token (row of 384), 8 tokens / block
__global__ void __launch_bounds__(256) ln_gelu_kernel(const float* __restrict__ x,
                                                      const float* __restrict__ lw,
                                                      const float* __restrict__ lb) {
    int w = threadIdx.x >> 5, lane = threadIdx.x & 31;
    size_t token = (size_t)blockIdx.x * 8 + w;
    const float4* xr = (const float4*)(x + token * C_);

    float4 v[3];
    float s = 0.f, sq = 0.f;
#pragma unroll
    for (int j = 0; j < 3; j++) {
        v[j] = xr[lane + 32 * j];
        s  += v[j].x + v[j].y + v[j].z + v[j].w;
        sq += v[j].x * v[j].x + v[j].y * v[j].y + v[j].z * v[j].z + v[j].w * v[j].w;
    }
#pragma unroll
    for (int o = 16; o; o >>= 1) {
        s  += __shfl_xor_sync(0xffffffffu, s, o);
        sq += __shfl_xor_sync(0xffffffffu, sq, o);
    }
    float mean = s * (1.0f / 384.0f);
    float var  = sq * (1.0f / 384.0f) - mean * mean;
    float inv  = rsqrtf(var + 1e-6f);

    float4* yr = (float4*)(g_xg + token * C_);
#pragma unroll
    for (int j = 0; j < 3; j++) {
        int f = lane + 32 * j;
        float4 wv = ((const float4*)lw)[f];
        float4 bv = ((const float4*)lb)[f];
        float4 o4;
        o4.x = gelu_exact((v[j].x - mean) * inv * wv.x + bv.x);
        o4.y = gelu_exact((v[j].y - mean) * inv * wv.y + bv.y);
        o4.z = gelu_exact((v[j].z - mean) * inv * wv.z + bv.z);
        o4.w = gelu_exact((v[j].w - mean) * inv * wv.w + bv.w);
        yr[f] = o4;
    }
}

// ---------------- kernel 2/5: tf32 GEMM  C[r,c] = sum_k A[r,k]*B[c,k] (+bias)
// tiles: 128(M) x 64(N) x 32(K). 8 warps, each 32x32.
// mode 0: A=g_xg, C=g_kv (kv projection). mode 1: A=g_ao, C=Cext (proj + bias).
__global__ void __launch_bounds__(256) gemm_tf32_kernel(const float* __restrict__ Bw,
                                                        const float* __restrict__ bias,
                                                        float* __restrict__ Cext,
                                                        int mode, int ldc) {
    __shared__ uint32_t As[128 * 36];
    __shared__ uint32_t Bs[64 * 36];

    const float* A = (mode == 0) ? g_xg : g_ao;
    float* Cm = (mode == 0) ? g_kv : Cext;

    int tid = threadIdx.x, w = tid >> 5, lane = tid & 31, g = lane >> 2, t = lane & 3;
    size_t m0 = (size_t)blockIdx.y * 128;
    int n0 = blockIdx.x * 64;
    int wr = w >> 1, wc = w & 1;

    float acc[2][4][4];
#pragma unroll
    for (int mt = 0; mt < 2; mt++)
#pragma unroll
        for (int nt = 0; nt < 4; nt++)
#pragma unroll
            for (int e = 0; e < 4; e++) acc[mt][nt][e] = 0.f;

    for (int kc = 0; kc < 384; kc += 32) {
#pragma unroll
        for (int it = 0; it < 4; it++) {            // A tile: 128x32
            int idx = tid + it * 256;
            int r = idx >> 3, j = (idx & 7) * 4;
            float4 va = *(const float4*)(A + (m0 + r) * 384 + kc + j);
            As[r * 36 + j]     = f2tf(va.x);
            As[r * 36 + j + 1] = f2tf(va.y);
            As[r * 36 + j + 2] = f2tf(va.z);
            As[r * 36 + j + 3] = f2tf(va.w);
        }
#pragma unroll
        for (int it = 0; it < 2; it++) {            // B tile: 64x32
            int idx = tid + it * 256;
            int r = idx >> 3, j = (idx & 7) * 4;
            float4 vb = *(const float4*)(Bw + (size_t)(n0 + r) * 384 + kc + j);
            Bs[r * 36 + j]     = f2tf(vb.x);
            Bs[r * 36 + j + 1] = f2tf(vb.y);
            Bs[r * 36 + j + 2] = f2tf(vb.z);
            Bs[r * 36 + j + 3] = f2tf(vb.w);
        }
        __syncthreads();

#pragma unroll
        for (int ks = 0; ks < 4; ks++) {
            int kk = ks * 8;
            uint32_t af[2][4], bf[4][2];
#pragma unroll
            for (int mt = 0; mt < 2; mt++) {
                int r0 = wr * 32 + mt * 16 + g;
                af[mt][0] = As[r0 * 36 + kk + t];
                af[mt][1] = As[(r0 + 8) * 36 + kk + t];
                af[mt][2] = As[r0 * 36 + kk + t + 4];
                af[mt][3] = As[(r0 + 8) * 36 + kk + t + 4];
            }
#pragma unroll
            for (int nt = 0; nt < 4; nt++) {
                int c0 = wc * 32 + nt * 8 + g;
                bf[nt][0] = Bs[c0 * 36 + kk + t];
                bf[nt][1] = Bs[c0 * 36 + kk + t + 4];
            }
#pragma unroll
            for (int mt = 0; mt < 2; mt++)
#pragma unroll
                for (int nt = 0; nt < 4; nt++) mma8(acc[mt][nt], af[mt], bf[nt]);
        }
        __syncthreads();
    }

#pragma unroll
    for (int mt = 0; mt < 2; mt++) {
        size_t r0 = m0 + wr * 32 + mt * 16 + g;
#pragma unroll
        for (int nt = 0; nt < 4; nt++) {
            int c = n0 + wc * 32 + nt * 8 + 2 * t;
            float b0 = bias ? bias[c] : 0.f;
            float b1 = bias ? bias[c + 1] : 0.f;
            Cm[r0 * ldc + c]           = acc[mt][nt][0] + b0;
            Cm[r0 * ldc + c + 1]       = acc[mt][nt][1] + b1;
            Cm[(r0 + 8) * ldc + c]     = acc[mt][nt][2] + b0;
            Cm[(r0 + 8) * ldc + c + 1] = acc[mt][nt][3] + b1;
        }
    }
}

// ---------------- kernel 3: fused attention (split over n) -------------------
// block = (split, b*8+h). M padded to 256 rows (16 m-tiles, 2 per warp).
// chunk of 64 n at a time: S = Q K^T (mma), P = exp(S) (no max needed: |logits| << 1),
// O += P V (mma, P via smem), den += rowsum(P). Writes partial num/den.
__global__ void __launch_bounds__(256) attn_kernel(const float* __restrict__ qp) {
    extern __shared__ uint32_t sh[];
    uint32_t* PQ = sh;               // [256][68] — Q (cols 0..47) then reused as P
    uint32_t* Ks = sh + 256 * 68;    // [64][52]
    uint32_t* Vs = Ks + 64 * 52;     // [64][56]

    int tid = threadIdx.x, w = tid >> 5, lane = tid & 31, g = lane >> 2, t = lane & 3;
    int bh = blockIdx.y, b = bh >> 3, h = bh & 7, split = blockIdx.x;

    // stage Q (tf32) rows 0..195, zero-pad to 255
    for (int idx = tid; idx < 256 * 12; idx += 256) {
        int m = idx / 12, j = (idx - m * 12) * 4;
        float4 q4 = make_float4(0.f, 0.f, 0.f, 0.f);
        if (m < 196) q4 = *(const float4*)(qp + m * 384 + h * 48 + j);
        PQ[m * 68 + j]     = f2tf(q4.x);
        PQ[m * 68 + j + 1] = f2tf(q4.y);
        PQ[m * 68 + j + 2] = f2tf(q4.z);
        PQ[m * 68 + j + 3] = f2tf(q4.w);
    }
    __syncthreads();

    // cache Q fragments in registers (2 m-tiles x 6 k-tiles per warp)
    uint32_t qa[2][6][4];
#pragma unroll
    for (int mt = 0; mt < 2; mt++) {
        int r0 = (w + 8 * mt) * 16 + g;
#pragma unroll
        for (int kt = 0; kt < 6; kt++) {
            int kk = kt * 8;
            qa[mt][kt][0] = PQ[r0 * 68 + kk + t];
            qa[mt][kt][1] = PQ[(r0 + 8) * 68 + kk + t];
            qa[mt][kt][2] = PQ[r0 * 68 + kk + t + 4];
            qa[mt][kt][3] = PQ[(r0 + 8) * 68 + kk + t + 4];
        }
    }
    __syncthreads();  // everyone done reading Q before PQ becomes P

    float o[2][6][4];
#pragma unroll
    for (int mt = 0; mt < 2; mt++)
#pragma unroll
        for (int dt = 0; dt < 6; dt++)
#pragma unroll
            for (int e = 0; e < 4; e++) o[mt][dt][e] = 0.f;
    float den[2][2] = {{0.f, 0.f}, {0.f, 0.f}};

    const float* kvb = g_kv + (size_t)b * N_ * 768;

    for (int c = 0; c < CPS; c++) {
        int n0 = split * 448 + c * 64;
        // stage K/V chunk (tf32)
        for (int idx = tid; idx < 64 * 12; idx += 256) {
            int i = idx / 12, j = (idx - i * 12) * 4;
            const float* rp = kvb + (size_t)(n0 + i) * 768 + h * 48 + j;
            float4 k4 = *(const float4*)rp;
            float4 v4 = *(const float4*)(rp + 384);
            Ks[i * 52 + j]     = f2tf(k4.x);
            Ks[i * 52 + j + 1] = f2tf(k4.y);
            Ks[i * 52 + j + 2] = f2tf(k4.z);
            Ks[i * 52 + j + 3] = f2tf(k4.w);
            Vs[i * 56 + j]     = f2tf(v4.x);
            Vs[i * 56 + j + 1] = f2tf(v4.y);
            Vs[i * 56 + j + 2] = f2tf(v4.z);
            Vs[i * 56 + j + 3] = f2tf(v4.w);
        }
        __syncthreads();

        // S = Q K^T : [2x16 m] x [64 n]
        float s[2][8][4];
#pragma unroll
        for (int mt = 0; mt < 2; mt++)
#pragma unroll
            for (int nt = 0; nt < 8; nt++)
#pragma unroll
                for (int e = 0; e < 4; e++) s[mt][nt][e] = 0.f;
#pragma unroll
        for (int kt = 0; kt < 6; kt++) {
            int kk = kt * 8;
            uint32_t bf[8][2];
#pragma unroll
            for (int nt = 0; nt < 8; nt++) {
                int r = (nt * 8 + g) * 52 + kk;
                bf[nt][0] = Ks[r + t];
                bf[nt][1] = Ks[r + t + 4];
            }
#pragma unroll
            for (int mt = 0; mt < 2; mt++)
#pragma unroll
                for (int nt = 0; nt < 8; nt++) mma8(s[mt][nt], qa[mt][kt], bf[nt]);
        }

        // P = exp(S); accumulate den; stash P (tf32) into smem for PV mma
#pragma unroll
        for (int mt = 0; mt < 2; mt++) {
            int r0 = (w + 8 * mt) * 16 + g;
#pragma unroll
            for (int nt = 0; nt < 8; nt++) {
                int cc = nt * 8 + 2 * t;
                float p0 = __expf(s[mt][nt][0]);
                float p1 = __expf(s[mt][nt][1]);
                float p2 = __expf(s[mt][nt][2]);
                float p3 = __expf(s[mt][nt][3]);
                den[mt][0] += p0 + p1;
                den[mt][1] += p2 + p3;
                PQ[r0 * 68 + cc]           = f2tf(p0);
                PQ[r0 * 68 + cc + 1]       = f2tf(p1);
                PQ[(r0 + 8) * 68 + cc]     = f2tf(p2);
                PQ[(r0 + 8) * 68 + cc + 1] = f2tf(p3);
            }
        }
        __syncwarp();  // P rows are warp-private; only warp-level ordering needed

        // O += P V : k-dim = 64 (chunk), n-dim = 48 (head dim)
#pragma unroll
        for (int ks = 0; ks < 8; ks++) {
            int kk = ks * 8;
            uint32_t pa[2][4];
#pragma unroll
            for (int mt = 0; mt < 2; mt++) {
                int r0 = (w + 8 * mt) * 16 + g;
                pa[mt][0] = PQ[r0 * 68 + kk + t];
                pa[mt][1] = PQ[(r0 + 8) * 68 + kk + t];
                pa[mt][2] = PQ[r0 * 68 + kk + t + 4];
                pa[mt][3] = PQ[(r0 + 8) * 68 + kk + t + 4];
            }
#pragma unroll
            for (int dt = 0; dt < 6; dt++) {
                uint32_t vb[2];
                vb[0] = Vs[(kk + t) * 56 + dt * 8 + g];
                vb[1] = Vs[(kk + t + 4) * 56 + dt * 8 + g];
                mma8(o[0][dt], pa[0], vb);
                mma8(o[1][dt], pa[1], vb);
            }
        }
        __syncthreads();  // before next chunk overwrites Ks/Vs
    }

    // finalize den across the 4 threads sharing each row (lanes g*4 + t)
#pragma unroll
    for (int mt = 0; mt < 2; mt++) {
#pragma unroll
        for (int rr = 0; rr < 2; rr++) {
            den[mt][rr] += __shfl_xor_sync(0xffffffffu, den[mt][rr], 1);
            den[mt][rr] += __shfl_xor_sync(0xffffffffu, den[mt][rr], 2);
        }
    }

    float* op = g_opart + (size_t)(split * 256 + b * 8 + h) * M_ * DH;
    float* dp = g_den + (size_t)(split * 256 + b * 8 + h) * M_;
#pragma unroll
    for (int mt = 0; mt < 2; mt++) {
        int mr = (w + 8 * mt) * 16;
        int m0r = mr + g, m1r = mr + g + 8;
        if (m0r < 196) {
#pragma unroll
            for (int dt = 0; dt < 6; dt++) {
                int d = dt * 8 + 2 * t;
                op[m0r * 48 + d]     = o[mt][dt][0];
                op[m0r * 48 + d + 1] = o[mt][dt][1];
            }
            if (t == 0) dp[m0r] = den[mt][0];
        }
        if (m1r < 196) {
#pragma unroll
            for (int dt = 0; dt < 6; dt++) {
                int d = dt * 8 + 2 * t;
                op[m1r * 48 + d]     = o[mt][dt][2];
                op[m1r * 48 + d + 1] = o[mt][dt][3];
            }
            if (t == 0) dp[m1r] = den[mt][1];
        }
    }
}

// ---------------- kernel 4: combine split partials ---------------------------
__global__ void __launch_bounds__(256) combine_kernel() {
    size_t idx = (size_t)blockIdx.x * 256 + threadIdx.x;  // [b][m][h][d], 2408448 total
    int d = (int)(idx % 48);
    size_t r = idx / 48;
    int h = (int)(r & 7);
    r >>= 3;
    int m = (int)(r % 196);
    int b = (int)(r / 196);

    float num = 0.f, dd = 0.f;
#pragma unroll
    for (int s = 0; s < SPLITS; s++) {
        size_t base = (size_t)(s * 256 + b * 8 + h);
        num += g_opart[base * (M_ * DH) + m * 48 + d];
        dd  += g_den[base * M_ + m];
    }
    g_ao[idx] = num / dd;
}

// ---------------- launch -----------------------------------------------------
extern "C" void kernel_launch(void* const* d_in, const int* in_sizes, int n_in,
                              void* d_out, int out_size) {
    const float* x   = (const float*)d_in[0];
    const float* qp  = (const float*)d_in[1];
    const float* kvw = (const float*)d_in[2];
    const float* pw  = (const float*)d_in[3];
    const float* pb  = (const float*)d_in[4];
    const float* lw  = (const float*)d_in[5];
    const float* lb  = (const float*)d_in[6];
    float* out = (float*)d_out;

    // 1) LayerNorm + GELU
    ln_gelu_kernel<<<BN / 8, 256>>>(x, lw, lb);

    // 2) kv = xg @ kv_w^T  -> g_kv [BN, 768]
    gemm_tf32_kernel<<<dim3(768 / 64, BN / 128), 256>>>(kvw, nullptr, nullptr, 0, 768);

    // 3) attention (split over n), partial num/den
    const int attn_smem = (256 * 68 + 64 * 52 + 64 * 56) * 4;  // 97280 B
    cudaFuncSetAttribute(attn_kernel, cudaFuncAttributeMaxDynamicSharedMemorySize, attn_smem);
    attn_kernel<<<dim3(SPLITS, B_ * H_), 256, attn_smem>>>(qp);

    // 4) combine splits -> g_ao [B*M, 384]
    combine_kernel<<<(B_ * M_ * C_) / 256, 256>>>();

    // 5) out = g_ao @ proj_w^T + proj_b
    gemm_tf32_kernel<<<dim3(384 / 64, (B_ * M_) / 128), 256>>>(pw, pb, out, 1, 384);
}

// round 2
// speedup vs baseline: 1.0985x; 1.0985x over previous
#include <cuda_runtime.h>
#include <cstdint>
#include <cstddef>

// Problem constants
#define B_  32
#define N_  3136
#define C_  384
#define H_  8
#define DH  48
#define M_  196
#define BN  100352           // B_*N_
#define SPLITS 7             // attention n-splits
#define CPS    7             // chunks (of 64) per split: 7*7*64 = 3136
#define PROJ_ROWS 6272       // B_*M_
#define PROJ_ROWS_PAD 6400

// ---------------- scratch (device globals; no allocation allowed) ----------
__device__ float g_xg[(size_t)BN * C_];                         // LN+GELU output (tf32-rounded)
__device__ float g_kv[(size_t)BN * 2 * C_];                     // kv projection (tf32-rounded)
__device__ float g_opart[(size_t)SPLITS * B_ * H_ * M_ * DH];   // attention partial numerators
__device__ float g_den[(size_t)SPLITS * B_ * H_ * M_];          // attention partial denominators
__device__ float g_ao[(size_t)PROJ_ROWS_PAD * C_];              // attention output (tf32-rounded, padded rows)
__device__ float g_wkv[768 * 384];                              // tf32-rounded kv weights
__device__ float g_wp[384 * 384];                               // tf32-rounded proj weights
__device__ float g_q[196 * 384];                                // tf32-rounded queries

// ---------------- helpers ---------------------------------------------------
__device__ __forceinline__ uint32_t f2tf(float f) {
    uint32_t u;
    asm("cvt.rna.tf32.f32 %0, %1;" : "=r"(u) : "f"(f));
    return u;
}
__device__ __forceinline__ float rtf(float f) { return __uint_as_float(f2tf(f)); }

__device__ __forceinline__ void mma8(float d[4], const uint32_t a[4], const uint32_t b[2]) {
    asm("mma.sync.aligned.m16n8k8.row.col.f32.tf32.tf32.f32 "
        "{%0,%1,%2,%3},{%4,%5,%6,%7},{%8,%9},{%0,%1,%2,%3};"
        : "+f"(d[0]), "+f"(d[1]), "+f"(d[2]), "+f"(d[3])
        : "r"(a[0]), "r"(a[1]), "r"(a[2]), "r"(a[3]), "r"(b[0]), "r"(b[1]));
}

__device__ __forceinline__ float gelu_exact(float y) {
    return 0.5f * y * (1.0f + erff(y * 0.7071067811865475f));
}

__device__ __forceinline__ uint32_t s2u(const void* p) {
    uint32_t a;
    asm("{ .reg .u64 t; cvta.to.shared.u64 t, %1; cvt.u32.u64 %0, t; }" : "=r"(a) : "l"(p));
    return a;
}
__device__ __forceinline__ void cp16(uint32_t s, const void* g) {
    asm volatile("cp.async.cg.shared.global [%0], [%1], 16;" :: "r"(s), "l"(g));
}

// ---------------- kernel 1: LayerNorm + exact GELU (tf32-rounded output) ----
__global__ void __launch_bounds__(256) ln_gelu_kernel(const float* __restrict__ x,
                                                      const float* __restrict__ lw,
                                                      const float* __restrict__ lb) {
    int w = threadIdx.x >> 5, lane = threadIdx.x & 31;
    size_t token = (size_t)blockIdx.x * 8 + w;
    const float4* xr = (const float4*)(x + token * C_);

    float4 v[3];
    float s = 0.f, sq = 0.f;
#pragma unroll
    for (int j = 0; j < 3; j++) {
        v[j] = xr[lane + 32 * j];
        s  += v[j].x + v[j].y + v[j].z + v[j].w;
        sq += v[j].x * v[j].x + v[j].y * v[j].y + v[j].z * v[j].z + v[j].w * v[j].w;
    }
#pragma unroll
    for (int o = 16; o; o >>= 1) {
        s  += __shfl_xor_sync(0xffffffffu, s, o);
        sq += __shfl_xor_sync(0xffffffffu, sq, o);
    }
    float mean = s * (1.0f / 384.0f);
    float var  = sq * (1.0f / 384.0f) - mean * mean;
    float inv  = rsqrtf(var + 1e-6f);

    uint4* yr = (uint4*)(g_xg + token * C_);
#pragma unroll
    for (int j = 0; j < 3; j++) {
        int f = lane + 32 * j;
        float4 wv = ((const float4*)lw)[f];
        float4 bv = ((const float4*)lb)[f];
        uint4 o4;
        o4.x = f2tf(gelu_exact((v[j].x - mean) * inv * wv.x + bv.x));
        o4.y = f2tf(gelu_exact((v[j].y - mean) * inv * wv.y + bv.y));
        o4.z = f2tf(gelu_exact((v[j].z - mean) * inv * wv.z + bv.z));
        o4.w = f2tf(gelu_exact((v[j].w - mean) * inv * wv.w + bv.w));
        yr[f] = o4;
    }
}

// ---------------- kernel 1b: pre-round weights & queries to tf32 -------------
__global__ void __launch_bounds__(256) wcvt_kernel(const float* __restrict__ kvw,
                                                   const float* __restrict__ pw,
                                                   const float* __restrict__ qp) {
    int i = blockIdx.x * 256 + threadIdx.x;   // grid covers 768*384 exactly
    g_wkv[i] = rtf(kvw[i]);
    if (i < 384 * 384) g_wp[i] = rtf(pw[i]);
    if (i < 196 * 384) g_q[i]  = rtf(qp[i]);
}

// ---------------- kernel 2/5: tf32 GEMM, cp.async 3-stage pipeline -----------
// C[r,c] = sum_k A[r,k]*B[c,k] (+bias). Block tile 256x128x16; 8 warps 64x64.
// Operands are pre-rounded tf32 bit patterns -> no cvt anywhere.
// smem per stage: A 256x16 + B 128x16 words = 24576 B; 3 stages = 73728 B.
// Swizzle: word (r,k) at r*16 + (k ^ (((r>>1)&3)<<2))  -> conflict-free LDS+STS.
__global__ void __launch_bounds__(256, 1) gemm_tf32_kernel(const float* __restrict__ ext_bias,
                                                           float* __restrict__ Cext,
                                                           int mode) {
    extern __shared__ uint32_t sm[];
    const float* A  = mode ? g_ao : g_xg;
    const float* Bw = mode ? g_wp : g_wkv;
    float* Cm = mode ? Cext : g_kv;
    const int ldc   = mode ? 384 : 768;
    const int Mrows = mode ? PROJ_ROWS : BN;

    int tid = threadIdx.x, lane = tid & 31, w = tid >> 5, g = lane >> 2, t = lane & 3;
    int wm = w >> 1, wn = w & 1;                 // 4x2 warp grid, warp tile 64(M)x64(N)
    size_t m0 = (size_t)blockIdx.y * 256;
    int n0 = blockIdx.x * 128;

    uint32_t smu = s2u(sm);

    // per-thread cp.async assignments (float4 granularity)
    int jr = tid & 3;            // which float4 within the 16-wide k row
    int rb = tid >> 2;           // base row 0..63
    size_t   a_goff[4]; uint32_t a_soff[4];
#pragma unroll
    for (int l = 0; l < 4; l++) {
        int r = rb + l * 64;
        a_goff[l] = (m0 + (size_t)r) * 384 + jr * 4;
        a_soff[l] = (uint32_t)(r * 16 + ((jr * 4) ^ (((r >> 1) & 3) << 2))) * 4;
    }
    size_t   b_goff[2]; uint32_t b_soff[2];
#pragma unroll
    for (int l = 0; l < 2; l++) {
        int c = rb + l * 64;
        b_goff[l] = (size_t)(n0 + c) * 384 + jr * 4;
        b_soff[l] = (uint32_t)(c * 16 + ((jr * 4) ^ (((c >> 1) & 3) << 2))) * 4 + 16384;
    }

    float acc[4][8][4];
#pragma unroll
    for (int mt = 0; mt < 4; mt++)
#pragma unroll
        for (int nt = 0; nt < 8; nt++)
#pragma unroll
            for (int e = 0; e < 4; e++) acc[mt][nt][e] = 0.f;

    auto issue = [&](int s, int kc) {
        uint32_t sb = smu + s * 24576;
#pragma unroll
        for (int l = 0; l < 4; l++) cp16(sb + a_soff[l], A + a_goff[l] + kc);
#pragma unroll
        for (int l = 0; l < 2; l++) cp16(sb + b_soff[l], Bw + b_goff[l] + kc);
        asm volatile("cp.async.commit_group;");
    };

    issue(0, 0);
    issue(1, 16);

    int s = 0;
    for (int it = 0; it < 24; it++) {
        if (it < 23) asm volatile("cp.async.wait_group 1;");
        else         asm volatile("cp.async.wait_group 0;");
        __syncthreads();
        if (it + 2 < 24) issue((s + 2) % 3, (it + 2) * 16);

        uint32_t* As = sm + s * 6144;
        uint32_t* Bs = As + 4096;
#pragma unroll
        for (int ks = 0; ks < 2; ks++) {
            int kk = ks * 8;
            uint32_t af[4][4], bf[8][2];
#pragma unroll
            for (int mt = 0; mt < 4; mt++) {
                int r0 = wm * 64 + mt * 16 + g;
                int swa = ((r0 >> 1) & 3) << 2;
                int c0 = (kk + t) ^ swa, c1 = (kk + t + 4) ^ swa;
                af[mt][0] = As[r0 * 16 + c0];
                af[mt][1] = As[(r0 + 8) * 16 + c0];
                af[mt][2] = As[r0 * 16 + c1];
                af[mt][3] = As[(r0 + 8) * 16 + c1];
            }
#pragma unroll
            for (int nt = 0; nt < 8; nt++) {
                int cc = wn * 64 + nt * 8 + g;
                int swb = ((cc >> 1) & 3) << 2;
                bf[nt][0] = Bs[cc * 16 + ((kk + t) ^ swb)];
                bf[nt][1] = Bs[cc * 16 + ((kk + t + 4) ^ swb)];
            }
#pragma unroll
            for (int mt = 0; mt < 4; mt++)
#pragma unroll
                for (int nt = 0; nt < 8; nt++) mma8(acc[mt][nt], af[mt], bf[nt]);
        }
        s = (s == 2) ? 0 : s + 1;
    }

    // epilogue
#pragma unroll
    for (int mt = 0; mt < 4; mt++) {
        size_t r0 = m0 + wm * 64 + mt * 16 + g;
#pragma unroll
        for (int nt = 0; nt < 8; nt++) {
            int c = n0 + wn * 64 + nt * 8 + 2 * t;
            float b0 = 0.f, b1 = 0.f;
            if (mode) { b0 = ext_bias[c]; b1 = ext_bias[c + 1]; }
            float v00 = acc[mt][nt][0] + b0, v01 = acc[mt][nt][1] + b1;
            float v10 = acc[mt][nt][2] + b0, v11 = acc[mt][nt][3] + b1;
            if (!mode) { v00 = rtf(v00); v01 = rtf(v01); v10 = rtf(v10); v11 = rtf(v11); }
            if (r0 < (size_t)Mrows) {
                Cm[r0 * ldc + c]     = v00;
                Cm[r0 * ldc + c + 1] = v01;
            }
            if (r0 + 8 < (size_t)Mrows) {
                Cm[(r0 + 8) * ldc + c]     = v10;
                Cm[(r0 + 8) * ldc + c + 1] = v11;
            }
        }
    }
}

// ---------------- kernel 3: fused attention (split over n) -------------------
// Operands pre-rounded tf32: staging is a pure copy. P is rounded after exp.
__global__ void __launch_bounds__(256) attn_kernel() {
    extern __shared__ uint32_t sh[];
    uint32_t* PQ = sh;               // [256][68] — Q (cols 0..47) then reused as P
    uint32_t* Ks = sh + 256 * 68;    // [64][52]
    uint32_t* Vs = Ks + 64 * 52;     // [64][56]

    int tid = threadIdx.x, w = tid >> 5, lane = tid & 31, g = lane >> 2, t = lane & 3;
    int bh = blockIdx.y, b = bh >> 3, h = bh & 7, split = blockIdx.x;

    // stage Q rows 0..195, zero-pad to 255
    for (int idx = tid; idx < 256 * 12; idx += 256) {
        int m = idx / 12, j = (idx - m * 12) * 4;
        float4 q4 = make_float4(0.f, 0.f, 0.f, 0.f);
        if (m < 196) q4 = *(const float4*)(g_q + m * 384 + h * 48 + j);
        PQ[m * 68 + j]     = __float_as_uint(q4.x);
        PQ[m * 68 + j + 1] = __float_as_uint(q4.y);
        PQ[m * 68 + j + 2] = __float_as_uint(q4.z);
        PQ[m * 68 + j + 3] = __float_as_uint(q4.w);
    }
    __syncthreads();

    // cache Q fragments in registers (2 m-tiles x 6 k-tiles per warp)
    uint32_t qa[2][6][4];
#pragma unroll
    for (int mt = 0; mt < 2; mt++) {
        int r0 = (w + 8 * mt) * 16 + g;
#pragma unroll
        for (int kt = 0; kt < 6; kt++) {
            int kk = kt * 8;
            qa[mt][kt][0] = PQ[r0 * 68 + kk + t];
            qa[mt][kt][1] = PQ[(r0 + 8) * 68 + kk + t];
            qa[mt][kt][2] = PQ[r0 * 68 + kk + t + 4];
            qa[mt][kt][3] = PQ[(r0 + 8) * 68 + kk + t + 4];
        }
    }
    __syncthreads();  // everyone done reading Q before PQ becomes P

    float o[2][6][4];
#pragma unroll
    for (int mt = 0; mt < 2; mt++)
#pragma unroll
        for (int dt = 0; dt < 6; dt++)
#pragma unroll
            for (int e = 0; e < 4; e++) o[mt][dt][e] = 0.f;
    float den[2][2] = {{0.f, 0.f}, {0.f, 0.f}};

    const float* kvb = g_kv + (size_t)b * N_ * 768;

    for (int c = 0; c < CPS; c++) {
        int n0 = split * 448 + c * 64;
        // stage K/V chunk (pure copy)
        for (int idx = tid; idx < 64 * 12; idx += 256) {
            int i = idx / 12, j = (idx - i * 12) * 4;
            const float* rp = kvb + (size_t)(n0 + i) * 768 + h * 48 + j;
            float4 k4 = *(const float4*)rp;
            float4 v4 = *(const float4*)(rp + 384);
            Ks[i * 52 + j]     = __float_as_uint(k4.x);
            Ks[i * 52 + j + 1] = __float_as_uint(k4.y);
            Ks[i * 52 + j + 2] = __float_as_uint(k4.z);
            Ks[i * 52 + j + 3] = __float_as_uint(k4.w);
            Vs[i * 56 + j]     = __float_as_uint(v4.x);
            Vs[i * 56 + j + 1] = __float_as_uint(v4.y);
            Vs[i * 56 + j + 2] = __float_as_uint(v4.z);
            Vs[i * 56 + j + 3] = __float_as_uint(v4.w);
        }
        __syncthreads();

        // S = Q K^T
        float s[2][8][4];
#pragma unroll
        for (int mt = 0; mt < 2; mt++)
#pragma unroll
            for (int nt = 0; nt < 8; nt++)
#pragma unroll
                for (int e = 0; e < 4; e++) s[mt][nt][e] = 0.f;
#pragma unroll
        for (int kt = 0; kt < 6; kt++) {
            int kk = kt * 8;
            uint32_t bf[8][2];
#pragma unroll
            for (int nt = 0; nt < 8; nt++) {
                int r = (nt * 8 + g) * 52 + kk;
                bf[nt][0] = Ks[r + t];
                bf[nt][1] = Ks[r + t + 4];
            }
#pragma unroll
            for (int mt = 0; mt < 2; mt++)
#pragma unroll
                for (int nt = 0; nt < 8; nt++) mma8(s[mt][nt], qa[mt][kt], bf[nt]);
        }

        // P = exp(S); accumulate den; stash P (tf32) into smem for PV mma
#pragma unroll
        for (int mt = 0; mt < 2; mt++) {
            int r0 = (w + 8 * mt) * 16 + g;
#pragma unroll
            for (int nt = 0; nt < 8; nt++) {
                int cc = nt * 8 + 2 * t;
                float p0 = __expf(s[mt][nt][0]);
                float p1 = __expf(s[mt][nt][1]);
                float p2 = __expf(s[mt][nt][2]);
                float p3 = __expf(s[mt][nt][3]);
                den[mt][0] += p0 + p1;
                den[mt][1] += p2 + p3;
                PQ[r0 * 68 + cc]           = f2tf(p0);
                PQ[r0 * 68 + cc + 1]       = f2tf(p1);
                PQ[(r0 + 8) * 68 + cc]     = f2tf(p2);
                PQ[(r0 + 8) * 68 + cc + 1] = f2tf(p3);
            }
        }
        __syncwarp();  // P rows are warp-private

        // O += P V
#pragma unroll
        for (int ks = 0; ks < 8; ks++) {
            int kk = ks * 8;
            uint32_t pa[2][4];
#pragma unroll
            for (int mt = 0; mt < 2; mt++) {
                int r0 = (w + 8 * mt) * 16 + g;
                pa[mt][0] = PQ[r0 * 68 + kk + t];
                pa[mt][1] = PQ[(r0 + 8) * 68 + kk + t];
                pa[mt][2] = PQ[r0 * 68 + kk + t + 4];
                pa[mt][3] = PQ[(r0 + 8) * 68 + kk + t + 4];
            }
#pragma unroll
            for (int dt = 0; dt < 6; dt++) {
                uint32_t vb[2];
                vb[0] = Vs[(kk + t) * 56 + dt * 8 + g];
                vb[1] = Vs[(kk + t + 4) * 56 + dt * 8 + g];
                mma8(o[0][dt], pa[0], vb);
                mma8(o[1][dt], pa[1], vb);
            }
        }
        __syncthreads();
    }

    // finalize den across the 4 threads sharing each row
#pragma unroll
    for (int mt = 0; mt < 2; mt++) {
#pragma unroll
        for (int rr = 0; rr < 2; rr++) {
            den[mt][rr] += __shfl_xor_sync(0xffffffffu, den[mt][rr], 1);
            den[mt][rr] += __shfl_xor_sync(0xffffffffu, den[mt][rr], 2);
        }
    }

    float* op = g_opart + (size_t)(split * 256 + b * 8 + h) * M_ * DH;
    float* dp = g_den + (size_t)(split * 256 + b * 8 + h) * M_;
#pragma unroll
    for (int mt = 0; mt < 2; mt++) {
        int mr = (w + 8 * mt) * 16;
        int m0r = mr + g, m1r = mr + g + 8;
        if (m0r < 196) {
#pragma unroll
            for (int dt = 0; dt < 6; dt++) {
                int d = dt * 8 + 2 * t;
                op[m0r * 48 + d]     = o[mt][dt][0];
                op[m0r * 48 + d + 1] = o[mt][dt][1];
            }
            if (t == 0) dp[m0r] = den[mt][0];
        }
        if (m1r < 196) {
#pragma unroll
            for (int dt = 0; dt < 6; dt++) {
                int d = dt * 8 + 2 * t;
                op[m1r * 48 + d]     = o[mt][dt][2];
                op[m1r * 48 + d + 1] = o[mt][dt][3];
            }
            if (t == 0) dp[m1r] = den[mt][1];
        }
    }
}

// ---------------- kernel 4: combine split partials (tf32-rounded out) --------
__global__ void __launch_bounds__(256) combine_kernel() {
    size_t idx = (size_t)blockIdx.x * 256 + threadIdx.x;  // [b][m][h][d]
    int d = (int)(idx % 48);
    size_t r = idx / 48;
    int h = (int)(r & 7);
    r >>= 3;
    int m = (int)(r % 196);
    int b = (int)(r / 196);

    float num = 0.f, dd = 0.f;
#pragma unroll
    for (int s = 0; s < SPLITS; s++) {
        size_t base = (size_t)(s * 256 + b * 8 + h);
        num += g_opart[base * (M_ * DH) + m * 48 + d];
        dd  += g_den[base * M_ + m];
    }
    g_ao[idx] = rtf(num / dd);
}

// ---------------- launch -----------------------------------------------------
extern "C" void kernel_launch(void* const* d_in, const int* in_sizes, int n_in,
                              void* d_out, int out_size) {
    const float* x   = (const float*)d_in[0];
    const float* qp  = (const float*)d_in[1];
    const float* kvw = (const float*)d_in[2];
    const float* pw  = (const float*)d_in[3];
    const float* pb  = (const float*)d_in[4];
    const float* lw  = (const float*)d_in[5];
    const float* lb  = (const float*)d_in[6];
    float* out = (float*)d_out;

    // 1) LayerNorm + GELU (tf32-rounded out)
    ln_gelu_kernel<<<BN / 8, 256>>>(x, lw, lb);

    // 1b) pre-round weights + queries
    wcvt_kernel<<<(768 * 384) / 256, 256>>>(kvw, pw, qp);

    // 2) kv = xg @ kv_w^T  -> g_kv [BN, 768]
    const int gemm_smem = 3 * 24576;  // 73728 B
    cudaFuncSetAttribute(gemm_tf32_kernel, cudaFuncAttributeMaxDynamicSharedMemorySize, gemm_smem);
    gemm_tf32_kernel<<<dim3(768 / 128, BN / 256), 256, gemm_smem>>>(nullptr, nullptr, 0);

    // 3) attention (split over n), partial num/den
    const int attn_smem = (256 * 68 + 64 * 52 + 64 * 56) * 4;  // 97280 B
    cudaFuncSetAttribute(attn_kernel, cudaFuncAttributeMaxDynamicSharedMemorySize, attn_smem);
    attn_kernel<<<dim3(SPLITS, B_ * H_), 256, attn_smem>>>();

    // 4) combine splits -> g_ao [B*M, 384] (tf32-rounded)
    combine_kernel<<<(B_ * M_ * C_) / 256, 256>>>();

    // 5) out = g_ao @ proj_w^T + proj_b
    gemm_tf32_kernel<<<dim3(384 / 128, (PROJ_ROWS_PAD) / 256), 256, gemm_smem>>>(pb, out, 1);
}